// round 7
// baseline (speedup 1.0000x reference)
#include <cuda_runtime.h>
#include <cstdint>

#define BB 4
#define NN 1024
#define CC 1024
#define HH 16
#define HDIM 64

typedef unsigned long long ull;

// ---------------- scratch ----------------
static constexpr size_t OFF_Q   = 0;
static constexpr size_t OFF_K   = OFF_Q + (size_t)BB*HH*NN*HDIM;
static constexpr size_t OFF_VT  = OFF_K + (size_t)BB*HH*NN*HDIM;
static constexpr size_t OFF_MID = OFF_VT + (size_t)BB*HH*NN*HDIM;   // mid[b][n][c]
static constexpr size_t OFF_S   = OFF_MID + (size_t)BB*NN*CC;
static constexpr size_t SCRATCH_TOTAL = OFF_S + (size_t)BB*HH*NN*NN;
__device__ float g_scratch[SCRATCH_TOTAL];

// ---------------- f32x2 helpers ----------------
__device__ __forceinline__ ull splat2(float v) {
  ull r; asm("mov.b64 %0, {%1,%1};" : "=l"(r) : "f"(v)); return r;
}
__device__ __forceinline__ void fma2(ull& d, ull a, ull b) {
  asm("fma.rn.f32x2 %0, %1, %2, %0;" : "+l"(d) : "l"(a), "l"(b));
}
__device__ __forceinline__ float lo32(ull u) { return __uint_as_float((unsigned)u); }
__device__ __forceinline__ float hi32(ull u) { return __uint_as_float((unsigned)(u >> 32)); }

// =========================================================================
// g4_gemm: K-packed FMA2 GEMM. C[64 rows, 64 cols] per CTA, thread = 4x4
// (strided micro-tile). A[rows,K], B[cols,K] fp32 K-major. acc lanes pack
// (k even, k odd); epilogue folds lo+hi.
// EPI: 0 plain->O0, 1 qkv scatter (q*scale,k,vT,+bias), 2 AV->mid, 3 proj+bias
// =========================================================================
template <int EPI>
__global__ __launch_bounds__(256, 2) void g4_gemm(
    const float* __restrict__ Ag, const float* __restrict__ Bg,
    int lda, int ldb, int K, size_t batchA, size_t batchB,
    const float* __restrict__ bias,
    float* __restrict__ O0, float* __restrict__ O1, float* __restrict__ O2,
    int ldo, size_t batchO) {
  constexpr int SR = 20;                    // floats per row (16 + pad 4)
  __shared__ float As[2][64 * SR];
  __shared__ float Bs[2][64 * SR];

  const int tid = threadIdx.x;
  const int w = tid >> 5, lane = tid & 31;
  const int wr = (w & 3) * 16, wc = (w >> 2) * 32;
  const int rg = lane >> 3, cg = lane & 7;  // row/col offsets within warp tile
  const int rb = blockIdx.y * 64, ob = blockIdx.x * 64, z = blockIdx.z;
  const float* Ab = Ag + (size_t)z * batchA;
  const float* Bb = Bg + (size_t)z * batchB;
  const int lr = tid >> 2, lk = (tid & 3) << 2;   // staging coords

  ull acc[4][4];
#pragma unroll
  for (int ri = 0; ri < 4; ri++)
#pragma unroll
    for (int ci = 0; ci < 4; ci++) acc[ri][ci] = 0ULL;

  float4 pa, pb;
  auto loadA = [&](int k0) {
    pa = __ldg((const float4*)(Ab + (size_t)(rb + lr) * lda + k0 + lk));
  };
  auto loadB = [&](int k0) {
    pb = __ldg((const float4*)(Bb + (size_t)(ob + lr) * ldb + k0 + lk));
  };
  auto stage = [&](int s) {
    *(float4*)&As[s][lr * SR + lk] = pa;
    *(float4*)&Bs[s][lr * SR + lk] = pb;
  };

  loadA(0); loadB(0);
  stage(0);
  __syncthreads();

  const int KT = K >> 4;
  int s = 0;
  for (int kt = 0; kt < KT; kt++) {
    if (kt + 1 < KT) { loadA((kt + 1) << 4); loadB((kt + 1) << 4); }
#pragma unroll
    for (int ks = 0; ks < 4; ks++) {
      const int k0 = ks * 4;
      ull a2[4][2], b2[4][2];
#pragma unroll
      for (int ri = 0; ri < 4; ri++) {
        ulonglong2 u = *(const ulonglong2*)&As[s][(wr + rg + 4 * ri) * SR + k0];
        a2[ri][0] = u.x; a2[ri][1] = u.y;
      }
#pragma unroll
      for (int ci = 0; ci < 4; ci++) {
        ulonglong2 u = *(const ulonglong2*)&Bs[s][(wc + cg + 8 * ci) * SR + k0];
        b2[ci][0] = u.x; b2[ci][1] = u.y;
      }
#pragma unroll
      for (int ri = 0; ri < 4; ri++)
#pragma unroll
        for (int ci = 0; ci < 4; ci++) {
          fma2(acc[ri][ci], a2[ri][0], b2[ci][0]);
          fma2(acc[ri][ci], a2[ri][1], b2[ci][1]);
        }
    }
    if (kt + 1 < KT) {
      stage(s ^ 1);
      __syncthreads();
    }
    s ^= 1;
  }

  // ---- epilogue ----
#pragma unroll
  for (int ri = 0; ri < 4; ri++) {
    const int row = rb + wr + rg + 4 * ri;
#pragma unroll
    for (int ci = 0; ci < 4; ci++) {
      const int col = ob + wc + cg + 8 * ci;
      float v = lo32(acc[ri][ci]) + hi32(acc[ri][ci]);
      if (EPI == 0) {
        O0[(size_t)z * batchO + (size_t)row * ldo + col] = v;
      } else if (EPI == 1) {
        const int which = col >> 10, h = (col >> 6) & 15, d = col & 63;
        const int b = row >> 10, n = row & 1023;
        v += __ldg(bias + col);
        if (which == 0) {
          O0[(((size_t)b * HH + h) * NN + n) * HDIM + d] = v * 0.125f;
        } else if (which == 1) {
          O1[(((size_t)b * HH + h) * NN + n) * HDIM + d] = v;
        } else {
          O2[((((size_t)b * HH + h) * HDIM + d) << 10) + n] = v;
        }
      } else if (EPI == 2) {
        const int b = z >> 4, g = z & 15;
        O0[(((size_t)b << 10) + row) * CC + (g << 6) + col] = v;
      } else {
        O0[(size_t)row * ldo + col] = v + __ldg(bias + col);
      }
    }
  }
}

// ---------------- fused mix1 + softmax + mix2 (FMA2) — unchanged from R5 ----------------
__global__ __launch_bounds__(256) void fused_mix_softmax(
    const float* __restrict__ wl, const float* __restrict__ bl,
    const float* __restrict__ ww, const float* __restrict__ bw,
    const float* __restrict__ s, float* __restrict__ attn) {
  extern __shared__ float sm[];
  float* T = sm;
  float* wls  = sm + 16 * 1024;
  float* wwi  = wls + 256;
  float* bls  = wwi + 256;
  float* bws  = bls + 16;
  float* invs = bws + 16;
  const int n = blockIdx.x, b = blockIdx.y, tid = threadIdx.x;
  const int lane = tid & 31;
  wls[tid] = wl[tid];
  if (tid < 16) bls[tid] = bl[tid];
  __syncthreads();

  const float* sb = s + (((size_t)b * 16) << 20) + ((size_t)n << 10) + tid * 4;
  {
    ull sv[16][2];
#pragma unroll
    for (int h = 0; h < 16; h++) {
      float4 v = __ldg((const float4*)(sb + ((size_t)h << 20)));
      asm("mov.b64 %0, {%1,%2};" : "=l"(sv[h][0]) : "f"(v.x), "f"(v.y));
      asm("mov.b64 %0, {%1,%2};" : "=l"(sv[h][1]) : "f"(v.z), "f"(v.w));
    }
#pragma unroll
    for (int g = 0; g < 16; g++) {
      ull a0 = splat2(bls[g]), a1 = a0;
#pragma unroll
      for (int h = 0; h < 16; h++) {
        ull wsp = splat2(wls[g * 16 + h]);
        fma2(a0, wsp, sv[h][0]);
        fma2(a1, wsp, sv[h][1]);
      }
      *(float4*)&T[g * 1024 + tid * 4] = make_float4(lo32(a0), hi32(a0), lo32(a1), hi32(a1));
    }
  }
  __syncthreads();

  {
    const int g0 = (tid >> 5) * 2;
#pragma unroll
    for (int rr = 0; rr < 2; rr++) {
      float* row = &T[(g0 + rr) << 10];
      float v[32];
#pragma unroll
      for (int j = 0; j < 8; j++) {
        float4 x4 = *(const float4*)&row[lane * 4 + j * 128];
        v[j * 4 + 0] = x4.x; v[j * 4 + 1] = x4.y; v[j * 4 + 2] = x4.z; v[j * 4 + 3] = x4.w;
      }
      float mx = -1e30f;
#pragma unroll
      for (int i = 0; i < 32; i++) mx = fmaxf(mx, v[i]);
#pragma unroll
      for (int o = 16; o; o >>= 1) mx = fmaxf(mx, __shfl_xor_sync(0xffffffffu, mx, o));
      float sum = 0.f;
#pragma unroll
      for (int i = 0; i < 32; i++) { v[i] = __expf(v[i] - mx); sum += v[i]; }
#pragma unroll
      for (int o = 16; o; o >>= 1) sum += __shfl_xor_sync(0xffffffffu, sum, o);
#pragma unroll
      for (int j = 0; j < 8; j++)
        *(float4*)&row[lane * 4 + j * 128] =
            make_float4(v[j * 4 + 0], v[j * 4 + 1], v[j * 4 + 2], v[j * 4 + 3]);
      if (lane == 0) invs[g0 + rr] = 1.0f / sum;
    }
  }
  __syncthreads();
  wwi[tid] = ww[tid] * invs[tid & 15];
  if (tid < 16) bws[tid] = bw[tid];
  __syncthreads();

  float* ab = attn + (((size_t)b * 16) << 20) + ((size_t)n << 10) + tid * 4;
  {
    ull ev[16][2];
#pragma unroll
    for (int h = 0; h < 16; h++) {
      ulonglong2 u = *(const ulonglong2*)&T[h * 1024 + tid * 4];
      ev[h][0] = u.x; ev[h][1] = u.y;
    }
#pragma unroll
    for (int g = 0; g < 16; g++) {
      ull a0 = splat2(bws[g]), a1 = a0;
#pragma unroll
      for (int h = 0; h < 16; h++) {
        ull wsp = splat2(wwi[g * 16 + h]);
        fma2(a0, wsp, ev[h][0]);
        fma2(a1, wsp, ev[h][1]);
      }
      *(float4*)(ab + ((size_t)g << 20)) = make_float4(lo32(a0), hi32(a0), lo32(a1), hi32(a1));
    }
  }
}

// ---------------- launch ----------------
extern "C" void kernel_launch(void* const* d_in, const int* in_sizes, int n_in,
                              void* d_out, int out_size) {
  const float* x      = (const float*)d_in[0];
  const float* qkv_w  = (const float*)d_in[1];
  const float* qkv_b  = (const float*)d_in[2];
  const float* proj_w = (const float*)d_in[3];
  const float* proj_b = (const float*)d_in[4];
  const float* wl     = (const float*)d_in[5];
  const float* bl     = (const float*)d_in[6];
  const float* ww     = (const float*)d_in[7];
  const float* bw     = (const float*)d_in[8];
  float* out = (float*)d_out;
  float* attn = out + (size_t)BB * NN * CC;

  float* scratch = nullptr;
  cudaGetSymbolAddress((void**)&scratch, g_scratch);
  float* q   = scratch + OFF_Q;
  float* k   = scratch + OFF_K;
  float* vT  = scratch + OFF_VT;
  float* mid = scratch + OFF_MID;
  float* s   = scratch + OFF_S;

  const int FUSED_SMEM = (16 * 1024 + 256 + 256 + 16 + 16 + 16) * 4;
  cudaFuncSetAttribute(fused_mix_softmax, cudaFuncAttributeMaxDynamicSharedMemorySize, FUSED_SMEM);

  // 1) qkv = x @ qkv_w^T + b -> q(*0.125), k, vT
  g4_gemm<1><<<dim3(48, 64, 1), 256>>>(
      x, qkv_w, CC, CC, CC, 0, 0, qkv_b, q, k, vT, 0, 0);
  // 2) s[b,h] = q[b,h] @ k[b,h]^T  (64 batches, K=64)
  g4_gemm<0><<<dim3(16, 16, 64), 256>>>(
      q, k, HDIM, HDIM, HDIM, (size_t)NN * HDIM, (size_t)NN * HDIM, nullptr,
      s, nullptr, nullptr, NN, (size_t)NN * NN);
  // 3) fused pre-mix + softmax + post-mix -> final attn
  fused_mix_softmax<<<dim3(NN, BB), 256, FUSED_SMEM>>>(wl, bl, ww, bw, s, attn);
  // 4) mid[b][n][g*64+d] = attn[b,g] @ vT[b,g]^T  (64 batches, K=1024)
  g4_gemm<2><<<dim3(1, 16, 64), 256>>>(
      attn, vT, NN, NN, NN, (size_t)NN * NN, (size_t)HDIM * NN, nullptr,
      mid, nullptr, nullptr, 0, 0);
  // 5) out = mid @ proj_w^T + proj_b
  g4_gemm<3><<<dim3(16, 64, 1), 256>>>(
      mid, proj_w, CC, CC, CC, 0, 0, proj_b, out, nullptr, nullptr, CC, 0);
}

// round 8
// speedup vs baseline: 1.3020x; 1.3020x over previous
#include <cuda_runtime.h>
#include <cstdint>

#define BB 4
#define NN 1024
#define CC 1024
#define HH 16
#define HDIM 64

typedef unsigned long long ull;

// ---------------- scratch ----------------
static constexpr size_t OFF_Q   = 0;
static constexpr size_t OFF_K   = OFF_Q + (size_t)BB*HH*NN*HDIM;
static constexpr size_t OFF_VT  = OFF_K + (size_t)BB*HH*NN*HDIM;
static constexpr size_t OFF_MID = OFF_VT + (size_t)BB*HH*NN*HDIM;   // mid[b][n][c]
static constexpr size_t OFF_S   = OFF_MID + (size_t)BB*NN*CC;
static constexpr size_t SCRATCH_TOTAL = OFF_S + (size_t)BB*HH*NN*NN;
__device__ float g_scratch[SCRATCH_TOTAL];

// ---------------- f32x2 helpers ----------------
__device__ __forceinline__ ull splat2(float v) {
  ull r; asm("mov.b64 %0, {%1,%1};" : "=l"(r) : "f"(v)); return r;
}
__device__ __forceinline__ void fma2(ull& d, ull a, ull b) {
  asm("fma.rn.f32x2 %0, %1, %2, %0;" : "+l"(d) : "l"(a), "l"(b));
}
__device__ __forceinline__ float lo32(ull u) { return __uint_as_float((unsigned)u); }
__device__ __forceinline__ float hi32(ull u) { return __uint_as_float((unsigned)(u >> 32)); }

// =========================================================================
// g5_gemm: C[128 rows, 64 cols] per CTA; thread = 8 rows (4 fma2 pairs) x 4 cols.
// A[rows,K], B[cols,K] fp32 K-major. Double-buffered smem, transposed [k][row].
// EPI: 0 plain->O0, 1 qkv scatter (q*scale,k,vT,+bias), 2 AV->mid, 3 proj+bias
// =========================================================================
template <int EPI>
__global__ __launch_bounds__(256, 3) void g5_gemm(
    const float* __restrict__ Ag, const float* __restrict__ Bg,
    int lda, int ldb, int K, size_t batchA, size_t batchB,
    const float* __restrict__ bias,
    float* __restrict__ O0, float* __restrict__ O1, float* __restrict__ O2,
    int ldo, size_t batchO) {
  constexpr int SRA = 132;   // 128 rows + pad
  constexpr int SRB = 68;    // 64 cols + pad
  __shared__ float As[2][16 * SRA];
  __shared__ float Bs[2][16 * SRB];

  const int tid = threadIdx.x;
  const int ty = tid >> 4, tx = tid & 15;  // 16 x 16
  const int r0 = ty * 8, c0 = tx * 4;
  const int rb = blockIdx.y * 128, ob = blockIdx.x * 64, z = blockIdx.z;
  const float* Ab = Ag + (size_t)z * batchA;
  const float* Bb = Bg + (size_t)z * batchB;
  const int lr = tid >> 2, lk = (tid & 3) << 2;  // staging coords

  ull acc[4][4];
#pragma unroll
  for (int p = 0; p < 4; p++)
#pragma unroll
    for (int j = 0; j < 4; j++) acc[p][j] = 0ULL;

  float4 pa[2], pb;
  auto loadA = [&](int k0) {
#pragma unroll
    for (int i = 0; i < 2; i++)
      pa[i] = __ldg((const float4*)(Ab + (size_t)(rb + lr + i * 64) * lda + k0 + lk));
  };
  auto loadB = [&](int k0) {
    pb = __ldg((const float4*)(Bb + (size_t)(ob + lr) * ldb + k0 + lk));
  };
  auto stage = [&](int s) {
#pragma unroll
    for (int i = 0; i < 2; i++) {
      const int r = lr + i * 64;
      As[s][(lk + 0) * SRA + r] = pa[i].x; As[s][(lk + 1) * SRA + r] = pa[i].y;
      As[s][(lk + 2) * SRA + r] = pa[i].z; As[s][(lk + 3) * SRA + r] = pa[i].w;
    }
    Bs[s][(lk + 0) * SRB + lr] = pb.x; Bs[s][(lk + 1) * SRB + lr] = pb.y;
    Bs[s][(lk + 2) * SRB + lr] = pb.z; Bs[s][(lk + 3) * SRB + lr] = pb.w;
  };

  loadA(0); loadB(0);
  stage(0);
  __syncthreads();

  const int KT = K >> 4;
  int s = 0;
  for (int kt = 0; kt < KT; kt++) {
    if (kt + 1 < KT) { loadA((kt + 1) << 4); loadB((kt + 1) << 4); }
#pragma unroll
    for (int kk = 0; kk < 16; kk++) {
      // B fragment: 4 cols, splat each
      float4 bf = *(const float4*)&Bs[s][kk * SRB + c0];
      ull sb[4] = {splat2(bf.x), splat2(bf.y), splat2(bf.z), splat2(bf.w)};
      // A fragment: 8 rows = 4 packed pairs (broadcast within warp)
      const float* ar = &As[s][kk * SRA + r0];
      ulonglong2 u0 = *(const ulonglong2*)ar;
      ulonglong2 u1 = *(const ulonglong2*)(ar + 4);
      ull ap[4] = {u0.x, u0.y, u1.x, u1.y};
#pragma unroll
      for (int j = 0; j < 4; j++)
#pragma unroll
        for (int p = 0; p < 4; p++) fma2(acc[p][j], ap[p], sb[j]);
    }
    if (kt + 1 < KT) {
      stage(s ^ 1);
      __syncthreads();
    }
    s ^= 1;
  }

  // ---- epilogue: acc[p][j] -> rows (rb+r0+2p, +1), cols ob+c0+j ----
  float4 bi = make_float4(0.f, 0.f, 0.f, 0.f);
  if (EPI == 1 || EPI == 3) bi = __ldg((const float4*)(bias + ob + c0));
  const float bv[4] = {bi.x, bi.y, bi.z, bi.w};
#pragma unroll
  for (int p = 0; p < 4; p++) {
    const int r = rb + r0 + 2 * p;
    float lo[4], hi[4];
#pragma unroll
    for (int j = 0; j < 4; j++) { lo[j] = lo32(acc[p][j]); hi[j] = hi32(acc[p][j]); }
    if (EPI == 0) {
      float* p0 = O0 + (size_t)z * batchO + (size_t)r * ldo + ob + c0;
      *(float4*)p0 = make_float4(lo[0], lo[1], lo[2], lo[3]);
      *(float4*)(p0 + ldo) = make_float4(hi[0], hi[1], hi[2], hi[3]);
    } else if (EPI == 1) {
      const int cg = ob + c0;
      const int which = cg >> 10, h = (cg >> 6) & 15, d0 = cg & 63;
      const int b = r >> 10, n = r & 1023;
      if (which == 2) {
#pragma unroll
        for (int j = 0; j < 4; j++)
          *(float2*)(O2 + ((((size_t)b * HH + h) * HDIM + d0 + j) << 10) + n) =
              make_float2(lo[j] + bv[j], hi[j] + bv[j]);
      } else {
        float* dst = (which == 0) ? O0 : O1;
        const float sc = (which == 0) ? 0.125f : 1.0f;
        float* p0 = dst + (((size_t)b * HH + h) * NN + n) * HDIM + d0;
        *(float4*)p0 = make_float4((lo[0] + bv[0]) * sc, (lo[1] + bv[1]) * sc,
                                   (lo[2] + bv[2]) * sc, (lo[3] + bv[3]) * sc);
        *(float4*)(p0 + HDIM) = make_float4((hi[0] + bv[0]) * sc, (hi[1] + bv[1]) * sc,
                                            (hi[2] + bv[2]) * sc, (hi[3] + bv[3]) * sc);
      }
    } else if (EPI == 2) {
      const int b = z >> 4, g = z & 15;
      float* p0 = O0 + (((size_t)b << 10) + r) * CC + (g << 6) + c0;
      *(float4*)p0 = make_float4(lo[0], lo[1], lo[2], lo[3]);
      *(float4*)(p0 + CC) = make_float4(hi[0], hi[1], hi[2], hi[3]);
    } else {
      float* p0 = O0 + (size_t)r * ldo + ob + c0;
      *(float4*)p0 = make_float4(lo[0] + bv[0], lo[1] + bv[1], lo[2] + bv[2], lo[3] + bv[3]);
      *(float4*)(p0 + ldo) = make_float4(hi[0] + bv[0], hi[1] + bv[1], hi[2] + bv[2], hi[3] + bv[3]);
    }
  }
}

// ---------------- fused mix1 + softmax + mix2 (FMA2) — unchanged ----------------
__global__ __launch_bounds__(256) void fused_mix_softmax(
    const float* __restrict__ wl, const float* __restrict__ bl,
    const float* __restrict__ ww, const float* __restrict__ bw,
    const float* __restrict__ s, float* __restrict__ attn) {
  extern __shared__ float sm[];
  float* T = sm;
  float* wls  = sm + 16 * 1024;
  float* wwi  = wls + 256;
  float* bls  = wwi + 256;
  float* bws  = bls + 16;
  float* invs = bws + 16;
  const int n = blockIdx.x, b = blockIdx.y, tid = threadIdx.x;
  const int lane = tid & 31;
  wls[tid] = wl[tid];
  if (tid < 16) bls[tid] = bl[tid];
  __syncthreads();

  const float* sb = s + (((size_t)b * 16) << 20) + ((size_t)n << 10) + tid * 4;
  {
    ull sv[16][2];
#pragma unroll
    for (int h = 0; h < 16; h++) {
      float4 v = __ldg((const float4*)(sb + ((size_t)h << 20)));
      asm("mov.b64 %0, {%1,%2};" : "=l"(sv[h][0]) : "f"(v.x), "f"(v.y));
      asm("mov.b64 %0, {%1,%2};" : "=l"(sv[h][1]) : "f"(v.z), "f"(v.w));
    }
#pragma unroll
    for (int g = 0; g < 16; g++) {
      ull a0 = splat2(bls[g]), a1 = a0;
#pragma unroll
      for (int h = 0; h < 16; h++) {
        ull wsp = splat2(wls[g * 16 + h]);
        fma2(a0, wsp, sv[h][0]);
        fma2(a1, wsp, sv[h][1]);
      }
      *(float4*)&T[g * 1024 + tid * 4] = make_float4(lo32(a0), hi32(a0), lo32(a1), hi32(a1));
    }
  }
  __syncthreads();

  {
    const int g0 = (tid >> 5) * 2;
#pragma unroll
    for (int rr = 0; rr < 2; rr++) {
      float* row = &T[(g0 + rr) << 10];
      float v[32];
#pragma unroll
      for (int j = 0; j < 8; j++) {
        float4 x4 = *(const float4*)&row[lane * 4 + j * 128];
        v[j * 4 + 0] = x4.x; v[j * 4 + 1] = x4.y; v[j * 4 + 2] = x4.z; v[j * 4 + 3] = x4.w;
      }
      float mx = -1e30f;
#pragma unroll
      for (int i = 0; i < 32; i++) mx = fmaxf(mx, v[i]);
#pragma unroll
      for (int o = 16; o; o >>= 1) mx = fmaxf(mx, __shfl_xor_sync(0xffffffffu, mx, o));
      float sum = 0.f;
#pragma unroll
      for (int i = 0; i < 32; i++) { v[i] = __expf(v[i] - mx); sum += v[i]; }
#pragma unroll
      for (int o = 16; o; o >>= 1) sum += __shfl_xor_sync(0xffffffffu, sum, o);
#pragma unroll
      for (int j = 0; j < 8; j++)
        *(float4*)&row[lane * 4 + j * 128] =
            make_float4(v[j * 4 + 0], v[j * 4 + 1], v[j * 4 + 2], v[j * 4 + 3]);
      if (lane == 0) invs[g0 + rr] = 1.0f / sum;
    }
  }
  __syncthreads();
  wwi[tid] = ww[tid] * invs[tid & 15];
  if (tid < 16) bws[tid] = bw[tid];
  __syncthreads();

  float* ab = attn + (((size_t)b * 16) << 20) + ((size_t)n << 10) + tid * 4;
  {
    ull ev[16][2];
#pragma unroll
    for (int h = 0; h < 16; h++) {
      ulonglong2 u = *(const ulonglong2*)&T[h * 1024 + tid * 4];
      ev[h][0] = u.x; ev[h][1] = u.y;
    }
#pragma unroll
    for (int g = 0; g < 16; g++) {
      ull a0 = splat2(bws[g]), a1 = a0;
#pragma unroll
      for (int h = 0; h < 16; h++) {
        ull wsp = splat2(wwi[g * 16 + h]);
        fma2(a0, wsp, ev[h][0]);
        fma2(a1, wsp, ev[h][1]);
      }
      *(float4*)(ab + ((size_t)g << 20)) = make_float4(lo32(a0), hi32(a0), lo32(a1), hi32(a1));
    }
  }
}

// ---------------- launch ----------------
extern "C" void kernel_launch(void* const* d_in, const int* in_sizes, int n_in,
                              void* d_out, int out_size) {
  const float* x      = (const float*)d_in[0];
  const float* qkv_w  = (const float*)d_in[1];
  const float* qkv_b  = (const float*)d_in[2];
  const float* proj_w = (const float*)d_in[3];
  const float* proj_b = (const float*)d_in[4];
  const float* wl     = (const float*)d_in[5];
  const float* bl     = (const float*)d_in[6];
  const float* ww     = (const float*)d_in[7];
  const float* bw     = (const float*)d_in[8];
  float* out = (float*)d_out;
  float* attn = out + (size_t)BB * NN * CC;

  float* scratch = nullptr;
  cudaGetSymbolAddress((void**)&scratch, g_scratch);
  float* q   = scratch + OFF_Q;
  float* k   = scratch + OFF_K;
  float* vT  = scratch + OFF_VT;
  float* mid = scratch + OFF_MID;
  float* s   = scratch + OFF_S;

  const int FUSED_SMEM = (16 * 1024 + 256 + 256 + 16 + 16 + 16) * 4;
  cudaFuncSetAttribute(fused_mix_softmax, cudaFuncAttributeMaxDynamicSharedMemorySize, FUSED_SMEM);

  // 1) qkv = x @ qkv_w^T + b -> q(*0.125), k, vT   (M=4096, N=3072, K=1024)
  g5_gemm<1><<<dim3(48, 32, 1), 256>>>(
      x, qkv_w, CC, CC, CC, 0, 0, qkv_b, q, k, vT, 0, 0);
  // 2) s[b,h] = q[b,h] @ k[b,h]^T  (64 batches, M=N=1024, K=64)
  g5_gemm<0><<<dim3(16, 8, 64), 256>>>(
      q, k, HDIM, HDIM, HDIM, (size_t)NN * HDIM, (size_t)NN * HDIM, nullptr,
      s, nullptr, nullptr, NN, (size_t)NN * NN);
  // 3) fused pre-mix + softmax + post-mix -> final attn
  fused_mix_softmax<<<dim3(NN, BB), 256, FUSED_SMEM>>>(wl, bl, ww, bw, s, attn);
  // 4) mid[b][n][g*64+d] = attn[b,g] @ vT[b,g]^T  (64 batches, M=1024, N=64, K=1024)
  g5_gemm<2><<<dim3(1, 8, 64), 256>>>(
      attn, vT, NN, NN, NN, (size_t)NN * NN, (size_t)HDIM * NN, nullptr,
      mid, nullptr, nullptr, 0, 0);
  // 5) out = mid @ proj_w^T + proj_b  (M=4096, N=1024, K=1024)
  g5_gemm<3><<<dim3(16, 32, 1), 256>>>(
      mid, proj_w, CC, CC, CC, 0, 0, proj_b, out, nullptr, nullptr, CC, 0);
}